// round 2
// baseline (speedup 1.0000x reference)
#include <cuda_runtime.h>
#include <math.h>

#define BB    16
#define TT    10240
#define CC    256
#define KERN  10
#define STRD  5
#define LOUT  2047
#define KST   12
#define NNEG  10
#define EPSV  1e-5f
#define TL    32          // l-rows per Q block
#define KG    4           // k's per Q block (grid.y = 3)

// -------- scratch (device globals; no allocation allowed) --------
__device__ float g_scale[CC];
__device__ float g_shift[CC];
__device__ float g_Q[(size_t)KST * BB * LOUT];

// packed f32x2 fma (FFMA2 in SASS; 2 FMAs per issue slot)
__device__ __forceinline__ float2 ffma2(float2 a, float2 b, float2 c) {
    unsigned long long ra = *reinterpret_cast<unsigned long long*>(&a);
    unsigned long long rb = *reinterpret_cast<unsigned long long*>(&b);
    unsigned long long rc = *reinterpret_cast<unsigned long long*>(&c);
    unsigned long long rd;
    asm("fma.rn.f32x2 %0, %1, %2, %3;" : "=l"(rd) : "l"(ra), "l"(rb), "l"(rc));
    return *reinterpret_cast<float2*>(&rd);
}

// -------- K1: conv+relu stats per channel -> BN scale/shift --------
__global__ __launch_bounds__(256) void k_stats(
    const float* __restrict__ x, const float* __restrict__ w,
    const float* __restrict__ bias, const float* __restrict__ gamma,
    const float* __restrict__ beta)
{
    int c = blockIdx.x;
    float wr[KERN];
#pragma unroll
    for (int i = 0; i < KERN; i++) wr[i] = w[c * KERN + i];
    float bc = bias[c];
    double s1 = 0.0, s2 = 0.0;
    for (int b = 0; b < BB; b++) {
        const float* xb = x + (size_t)b * TT;
        for (int l = threadIdx.x; l < LOUT; l += 256) {
            float h = bc;
#pragma unroll
            for (int i = 0; i < KERN; i++) h = fmaf(xb[l * STRD + i], wr[i], h);
            h = fmaxf(h, 0.0f);
            s1 += (double)h;
            s2 += (double)h * (double)h;
        }
    }
    __shared__ double r1[256], r2[256];
    r1[threadIdx.x] = s1; r2[threadIdx.x] = s2;
    __syncthreads();
    for (int off = 128; off; off >>= 1) {
        if (threadIdx.x < off) {
            r1[threadIdx.x] += r1[threadIdx.x + off];
            r2[threadIdx.x] += r2[threadIdx.x + off];
        }
        __syncthreads();
    }
    if (threadIdx.x == 0) {
        double N = (double)BB * LOUT;
        double mu = r1[0] / N;
        double var = r2[0] / N - mu * mu;
        double rs = 1.0 / sqrt(var + (double)EPSV);
        float sc = (float)((double)gamma[c] * rs);
        g_scale[c] = sc;
        g_shift[c] = beta[c] - (float)mu * sc;
    }
}

// -------- K2: conv+relu+BN affine -> d_out [B,C,L] (this IS z, transposed) ----
__global__ __launch_bounds__(256) void k_norm(
    const float* __restrict__ x, const float* __restrict__ w,
    const float* __restrict__ bias, float* __restrict__ out)
{
    int l = blockIdx.x * 256 + threadIdx.x;
    int c = blockIdx.y;
    int b = blockIdx.z;
    if (l >= LOUT) return;
    float wr[KERN];
#pragma unroll
    for (int i = 0; i < KERN; i++) wr[i] = __ldg(&w[c * KERN + i]);
    float h = __ldg(&bias[c]);
    const float* xb = x + (size_t)b * TT + (size_t)l * STRD;
#pragma unroll
    for (int i = 0; i < KERN; i++) h = fmaf(xb[i], wr[i], h);
    h = fmaxf(h, 0.0f);
    out[((size_t)b * CC + c) * LOUT + l] = fmaf(h, g_scale[c], g_shift[c]);
}

// -------- K3: Q[k,b,l] = z^T W_k z + b_k . z  (the 51.5 GFLOP part) --------
__global__ __launch_bounds__(256) void k_quad(
    const float* __restrict__ z,          // d_out, [B,C,L]
    const float* __restrict__ trw,        // [12,C,C]
    const float* __restrict__ trb)        // [12,C]
{
    const int tile = blockIdx.x;          // 0..1023  (b*64 + ltile)
    const int b    = tile >> 6;
    const int l0   = (tile & 63) * TL;
    const int kb   = blockIdx.y * KG;     // grid.y = 3
    const int t    = threadIdx.x;

    __shared__ float zsh[CC][TL + 2];     // stride 34 floats (even, 8B-aligned pairs)
    __shared__ float red[8][TL];

    // load z tile: zsh[c][l] = z[b, c, l0+l]; coalesced along l
    for (int i = t; i < CC * TL; i += 256) {
        int c = i >> 5, l = i & 31;
        int lg = l0 + l;
        zsh[c][l] = (lg < LOUT) ? z[((size_t)b * CC + c) * LOUT + lg] : 0.0f;
    }
    __syncthreads();

    for (int kk = 0; kk < KG; kk++) {
        const int k = kb + kk;
        const float* Wk = trw + (size_t)k * CC * CC + t;
        const float bkt = trb[k * CC + t];

        float2 u[TL / 2];
#pragma unroll
        for (int j = 0; j < TL / 2; j++) { u[j].x = bkt; u[j].y = bkt; }

#pragma unroll 4
        for (int c = 0; c < CC; c++) {
            float wv = __ldg(&Wk[(size_t)c * CC]);   // coalesced across t
            float2 w2 = make_float2(wv, wv);
#pragma unroll
            for (int j = 0; j < TL / 2; j++) {
                float2 z2 = *(const float2*)&zsh[c][2 * j];   // broadcast
                u[j] = ffma2(z2, w2, u[j]);
            }
        }

        // per-thread contribution to q_r: z[r,t] * u[r,t]
        float2 con[TL / 2];
#pragma unroll
        for (int j = 0; j < TL / 2; j++) {
            float2 z2 = *(const float2*)&zsh[t][2 * j];
            con[j].x = z2.x * u[j].x;
            con[j].y = z2.y * u[j].y;
        }
        // butterfly reduce across warp
#pragma unroll
        for (int m = 16; m; m >>= 1) {
#pragma unroll
            for (int j = 0; j < TL / 2; j++) {
                con[j].x += __shfl_xor_sync(0xffffffffu, con[j].x, m);
                con[j].y += __shfl_xor_sync(0xffffffffu, con[j].y, m);
            }
        }
        int warp = t >> 5, lane = t & 31;
        if (lane == 0) {
#pragma unroll
            for (int j = 0; j < TL / 2; j++) {
                red[warp][2 * j]     = con[j].x;
                red[warp][2 * j + 1] = con[j].y;
            }
        }
        __syncthreads();
        if (t < TL) {
            float q = 0.0f;
#pragma unroll
            for (int w8 = 0; w8 < 8; w8++) q += red[w8][t];
            int lg = l0 + t;
            if (lg < LOUT) g_Q[((size_t)k * BB + b) * LOUT + lg] = q;
        }
        __syncthreads();
    }
}

// -------- K4: losses, matching the reference's quirky reshape --------
// f (per batch b) flat order: idx = s*l_len + i, s in [0,11), i in [0,l_len).
// f_k row r = flat indices [11r, 11r+11) — rows straddle s boundaries!
// value(b,s,i): s==0 -> Q[b, k+i];  s>=1 -> Q[(b-s) mod 16, perm[k+i]]
__global__ __launch_bounds__(256) void k_loss(
    const int* __restrict__ perm, float* __restrict__ out_losses)
{
    const int k = blockIdx.x + 1;            // 1..12
    const int llen = LOUT - k;
    const float* Qk = g_Q + (size_t)(k - 1) * BB * LOUT;
    double acc = 0.0;
    const int total = BB * llen;             // number of softmax rows
    for (int g = threadIdx.x; g < total; g += 256) {
        int b = g / llen;
        int r = g - b * llen;
        int idx = 11 * r;
        int s = idx / llen;
        int i = idx - s * llen;
        float f[NNEG + 1];
#pragma unroll
        for (int j = 0; j <= NNEG; j++) {
            float v;
            if (s == 0) {
                v = Qk[b * LOUT + k + i];
            } else {
                int bb2 = (b - s) & (BB - 1);
                v = Qk[bb2 * LOUT + __ldg(&perm[k + i])];
            }
            f[j] = v;
            i++;
            if (i == llen) { i = 0; s++; }
        }
        float mx = f[0];
#pragma unroll
        for (int j = 1; j <= NNEG; j++) mx = fmaxf(mx, f[j]);
        float se = 0.0f, sf = 0.0f;
#pragma unroll
        for (int j = 0; j <= NNEG; j++) { se += __expf(f[j] - mx); sf += f[j]; }
        float lse = mx + __logf(se);
        acc += (double)((NNEG + 1) * lse - sf);
    }
    __shared__ double rsh[256];
    rsh[threadIdx.x] = acc;
    __syncthreads();
    for (int off = 128; off; off >>= 1) {
        if (threadIdx.x < off) rsh[threadIdx.x] += rsh[threadIdx.x + off];
        __syncthreads();
    }
    if (threadIdx.x == 0)
        out_losses[k - 1] = (float)(rsh[0] / ((double)(llen - k) * BB));
}

// -------- launch --------
extern "C" void kernel_launch(void* const* d_in, const int* in_sizes, int n_in,
                              void* d_out, int out_size)
{
    const float* x      = (const float*)d_in[0];
    const float* conv_w = (const float*)d_in[1];
    const float* conv_b = (const float*)d_in[2];
    const float* gamma  = (const float*)d_in[3];
    const float* beta   = (const float*)d_in[4];
    const float* trw    = (const float*)d_in[5];
    const float* trb    = (const float*)d_in[6];
    const int*   perm   = (const int*)d_in[7];
    float* out = (float*)d_out;

    k_stats<<<CC, 256>>>(x, conv_w, conv_b, gamma, beta);

    dim3 g2((LOUT + 255) / 256, CC, BB);
    k_norm<<<g2, 256>>>(x, conv_w, conv_b, out);

    dim3 g3(BB * 64, 3);   // 1024 row-tiles x 3 k-groups
    k_quad<<<g3, 256>>>(out, trw, trb);

    k_loss<<<KST, 256>>>(perm, out + (size_t)BB * CC * LOUT);
}

// round 3
// speedup vs baseline: 1.0607x; 1.0607x over previous
#include <cuda_runtime.h>
#include <math.h>

#define BB    16
#define TT    10240
#define CC    256
#define KERN  10
#define STRD  5
#define LOUT  2047
#define KST   12
#define NNEG  10
#define EPSV  1e-5f
#define TL    32          // l-rows per Q block
#define KG    4           // k's per Q block (grid.y = 3)
#define ZSTR  36          // smem row stride (floats): 144B, 16B-aligned

// -------- scratch (device globals; no allocation allowed) --------
__device__ float  g_scale[CC];
__device__ float  g_shift[CC];
__device__ float  g_Q[(size_t)KST * BB * LOUT];
__device__ double g_part[KST * BB];

// packed f32x2 fma (FFMA2 in SASS; 2 FMAs per issue slot)
__device__ __forceinline__ float2 ffma2(float2 a, float2 b, float2 c) {
    unsigned long long ra = *reinterpret_cast<unsigned long long*>(&a);
    unsigned long long rb = *reinterpret_cast<unsigned long long*>(&b);
    unsigned long long rc = *reinterpret_cast<unsigned long long*>(&c);
    unsigned long long rd;
    asm("fma.rn.f32x2 %0, %1, %2, %3;" : "=l"(rd) : "l"(ra), "l"(rb), "l"(rc));
    return *reinterpret_cast<float2*>(&rd);
}

// -------- K1: conv+relu stats per channel -> BN scale/shift --------
__global__ __launch_bounds__(256) void k_stats(
    const float* __restrict__ x, const float* __restrict__ w,
    const float* __restrict__ bias, const float* __restrict__ gamma,
    const float* __restrict__ beta)
{
    int c = blockIdx.x;
    float wr[KERN];
#pragma unroll
    for (int i = 0; i < KERN; i++) wr[i] = w[c * KERN + i];
    float bc = bias[c];
    double s1 = 0.0, s2 = 0.0;
    for (int b = 0; b < BB; b++) {
        const float* xb = x + (size_t)b * TT;
        for (int l = threadIdx.x; l < LOUT; l += 256) {
            float h = bc;
#pragma unroll
            for (int i = 0; i < KERN; i++) h = fmaf(xb[l * STRD + i], wr[i], h);
            h = fmaxf(h, 0.0f);
            s1 += (double)h;
            s2 += (double)h * (double)h;
        }
    }
    __shared__ double r1[256], r2[256];
    r1[threadIdx.x] = s1; r2[threadIdx.x] = s2;
    __syncthreads();
    for (int off = 128; off; off >>= 1) {
        if (threadIdx.x < off) {
            r1[threadIdx.x] += r1[threadIdx.x + off];
            r2[threadIdx.x] += r2[threadIdx.x + off];
        }
        __syncthreads();
    }
    if (threadIdx.x == 0) {
        double N = (double)BB * LOUT;
        double mu = r1[0] / N;
        double var = r2[0] / N - mu * mu;
        double rs = 1.0 / sqrt(var + (double)EPSV);
        float sc = (float)((double)gamma[c] * rs);
        g_scale[c] = sc;
        g_shift[c] = beta[c] - (float)mu * sc;
    }
}

// -------- K2: conv+relu+BN affine -> d_out [B,C,L] (this IS z, transposed) ----
__global__ __launch_bounds__(256) void k_norm(
    const float* __restrict__ x, const float* __restrict__ w,
    const float* __restrict__ bias, float* __restrict__ out)
{
    int l = blockIdx.x * 256 + threadIdx.x;
    int c = blockIdx.y;
    int b = blockIdx.z;
    if (l >= LOUT) return;
    float wr[KERN];
#pragma unroll
    for (int i = 0; i < KERN; i++) wr[i] = __ldg(&w[c * KERN + i]);
    float h = __ldg(&bias[c]);
    const float* xb = x + (size_t)b * TT + (size_t)l * STRD;
#pragma unroll
    for (int i = 0; i < KERN; i++) h = fmaf(xb[i], wr[i], h);
    h = fmaxf(h, 0.0f);
    out[((size_t)b * CC + c) * LOUT + l] = fmaf(h, g_scale[c], g_shift[c]);
}

// -------- K3: Q[k,b,l] = z^T W_k z + b_k . z  (the 51.5 GFLOP part) --------
// thread t = output column; TL=32 rows; W batch-prefetched 16-deep (MLP=16),
// z via LDS.128 broadcast, math as FFMA2 pairs (fp32 peak-rate path).
__global__ __launch_bounds__(256) void k_quad(
    const float* __restrict__ z,          // d_out, [B,C,L]
    const float* __restrict__ trw,        // [12,C,C]
    const float* __restrict__ trb)        // [12,C]
{
    const int tile = blockIdx.x;          // 0..1023  (b*64 + ltile)
    const int b    = tile >> 6;
    const int l0   = (tile & 63) * TL;
    const int kb   = blockIdx.y * KG;     // grid.y = 3
    const int t    = threadIdx.x;

    __shared__ float zsh[CC][ZSTR];       // rows 16B-aligned for LDS.128
    __shared__ float red[8][TL];

    // load z tile: zsh[c][l] = z[b, c, l0+l]; coalesced along l
    for (int i = t; i < CC * TL; i += 256) {
        int c = i >> 5, l = i & 31;
        int lg = l0 + l;
        zsh[c][l] = (lg < LOUT) ? z[((size_t)b * CC + c) * LOUT + lg] : 0.0f;
    }
    __syncthreads();

    for (int kk = 0; kk < KG; kk++) {
        const int k = kb + kk;
        const float* Wk = trw + (size_t)k * CC * CC + t;
        const float bkt = trb[k * CC + t];

        float2 u[TL / 2];
#pragma unroll
        for (int j = 0; j < TL / 2; j++) { u[j].x = bkt; u[j].y = bkt; }

        for (int c0 = 0; c0 < CC; c0 += 16) {
            // stage 1: 16 coalesced LDGs in flight (covers L2 latency)
            float wbuf[16];
#pragma unroll
            for (int i = 0; i < 16; i++)
                wbuf[i] = __ldg(&Wk[(size_t)(c0 + i) * CC]);
            // stage 2: 16 rank-1 update steps from registers + smem broadcast
#pragma unroll
            for (int i = 0; i < 16; i++) {
                float2 w2 = make_float2(wbuf[i], wbuf[i]);
                const float4* zp = (const float4*)&zsh[c0 + i][0];
#pragma unroll
                for (int j = 0; j < TL / 4; j++) {
                    float4 z4 = zp[j];                       // LDS.128 broadcast
                    u[2 * j]     = ffma2(make_float2(z4.x, z4.y), w2, u[2 * j]);
                    u[2 * j + 1] = ffma2(make_float2(z4.z, z4.w), w2, u[2 * j + 1]);
                }
            }
        }

        // per-thread contribution to q_r: z[r,t] * u[r,t]
        float2 con[TL / 2];
#pragma unroll
        for (int j = 0; j < TL / 2; j++) {
            float2 z2 = *(const float2*)&zsh[t][2 * j];
            con[j].x = z2.x * u[j].x;
            con[j].y = z2.y * u[j].y;
        }
        // butterfly reduce across warp
#pragma unroll
        for (int m = 16; m; m >>= 1) {
#pragma unroll
            for (int j = 0; j < TL / 2; j++) {
                con[j].x += __shfl_xor_sync(0xffffffffu, con[j].x, m);
                con[j].y += __shfl_xor_sync(0xffffffffu, con[j].y, m);
            }
        }
        int warp = t >> 5, lane = t & 31;
        if (lane == 0) {
#pragma unroll
            for (int j = 0; j < TL / 2; j++) {
                red[warp][2 * j]     = con[j].x;
                red[warp][2 * j + 1] = con[j].y;
            }
        }
        __syncthreads();
        if (t < TL) {
            float q = 0.0f;
#pragma unroll
            for (int w8 = 0; w8 < 8; w8++) q += red[w8][t];
            int lg = l0 + t;
            if (lg < LOUT) g_Q[((size_t)k * BB + b) * LOUT + lg] = q;
        }
        __syncthreads();
    }
}

// -------- K4a: per-(k,b) partial loss sums (deterministic tree reduce) --------
// f (per batch b) flat order: idx = s*l_len + i; row r = flat [11r, 11r+11)
// value(b,s,i): s==0 -> Q[b, k+i];  s>=1 -> Q[(b-s) mod 16, perm[k+i]]
__global__ __launch_bounds__(256) void k_loss_part(
    const int* __restrict__ perm)
{
    const int k = blockIdx.x + 1;            // 1..12
    const int b = blockIdx.y;                // 0..15
    const int llen = LOUT - k;
    const float* Qk = g_Q + (size_t)(k - 1) * BB * LOUT;
    double acc = 0.0;
    for (int r = threadIdx.x; r < llen; r += 256) {
        int idx = 11 * r;
        int s = idx / llen;
        int i = idx - s * llen;
        float f[NNEG + 1];
#pragma unroll
        for (int j = 0; j <= NNEG; j++) {
            float v;
            if (s == 0) {
                v = Qk[b * LOUT + k + i];
            } else {
                int bb2 = (b - s) & (BB - 1);
                v = Qk[bb2 * LOUT + __ldg(&perm[k + i])];
            }
            f[j] = v;
            i++;
            if (i == llen) { i = 0; s++; }
        }
        float mx = f[0];
#pragma unroll
        for (int j = 1; j <= NNEG; j++) mx = fmaxf(mx, f[j]);
        float se = 0.0f, sf = 0.0f;
#pragma unroll
        for (int j = 0; j <= NNEG; j++) { se += __expf(f[j] - mx); sf += f[j]; }
        float lse = mx + __logf(se);
        acc += (double)((NNEG + 1) * lse - sf);
    }
    __shared__ double rsh[256];
    rsh[threadIdx.x] = acc;
    __syncthreads();
    for (int off = 128; off; off >>= 1) {
        if (threadIdx.x < off) rsh[threadIdx.x] += rsh[threadIdx.x + off];
        __syncthreads();
    }
    if (threadIdx.x == 0)
        g_part[(k - 1) * BB + b] = rsh[0];
}

// -------- K4b: final 16-way sums -> 12 losses --------
__global__ __launch_bounds__(32) void k_loss_fin(float* __restrict__ out_losses)
{
    int kk = threadIdx.x;
    if (kk >= KST) return;
    int k = kk + 1;
    int llen = LOUT - k;
    double s = 0.0;
#pragma unroll
    for (int b = 0; b < BB; b++) s += g_part[kk * BB + b];
    out_losses[kk] = (float)(s / ((double)(llen - k) * BB));
}

// -------- launch --------
extern "C" void kernel_launch(void* const* d_in, const int* in_sizes, int n_in,
                              void* d_out, int out_size)
{
    const float* x      = (const float*)d_in[0];
    const float* conv_w = (const float*)d_in[1];
    const float* conv_b = (const float*)d_in[2];
    const float* gamma  = (const float*)d_in[3];
    const float* beta   = (const float*)d_in[4];
    const float* trw    = (const float*)d_in[5];
    const float* trb    = (const float*)d_in[6];
    const int*   perm   = (const int*)d_in[7];
    float* out = (float*)d_out;

    k_stats<<<CC, 256>>>(x, conv_w, conv_b, gamma, beta);

    dim3 g2((LOUT + 255) / 256, CC, BB);
    k_norm<<<g2, 256>>>(x, conv_w, conv_b, out);

    dim3 g3(BB * 64, 3);   // 1024 row-tiles x 3 k-groups
    k_quad<<<g3, 256>>>(out, trw, trb);

    dim3 g4(KST, BB);
    k_loss_part<<<g4, 256>>>(perm);
    k_loss_fin<<<1, 32>>>(out + (size_t)BB * CC * LOUT);
}

// round 5
// speedup vs baseline: 2.7273x; 2.5713x over previous
#include <cuda_runtime.h>
#include <cuda_bf16.h>
#include <math.h>
#include <stdint.h>

#define BB    16
#define TT    10240
#define CC    256
#define KERN  10
#define STRD  5
#define LOUT  2047
#define KST   12
#define NNEG  10
#define EPSV  1e-5f
#define RV    32752          // B*LOUT valid rows
#define RP    32768          // padded rows (256 tiles x 128)
#define NTILE 256            // M-tiles of 128

// ---- GEMM smem layout (bytes). Row stride 144B (36 banks) => conflict-free LDS.
#define OFF_AHI 0
#define OFF_ALO 18432
#define OFF_BHI 36864
#define OFF_BLO 73728
#define STAGE   110592
#define OFF_RED (2 * STAGE)               // 221184: float red[4][128]
#define SMEM_DYN (OFF_RED + 2048)         // 223232

// ---------------- device scratch (no allocation allowed) ----------------
__device__ __align__(16) float         g_scale[CC];
__device__ __align__(16) float         g_shift[CC];
__device__ __align__(16) float         g_Q[(size_t)KST * BB * LOUT];
__device__ __align__(16) double        g_part[KST * BB];
__device__ __align__(16) float         g_Zf [(size_t)RP * CC];
__device__ __align__(16) __nv_bfloat16 g_Zhi[(size_t)RP * CC];
__device__ __align__(16) __nv_bfloat16 g_Zlo[(size_t)RP * CC];
__device__ __align__(16) __nv_bfloat16 g_Whi[(size_t)KST * CC * CC];  // [k][n][c] = W[c][n]
__device__ __align__(16) __nv_bfloat16 g_Wlo[(size_t)KST * CC * CC];

// ---------------- helpers (baseline sm_80+ PTX only) ----------------
__device__ __forceinline__ uint32_t smem_u32(const void* p) {
    uint32_t a;
    asm("{ .reg .u64 t; cvta.to.shared.u64 t, %1; cvt.u32.u64 %0, t; }" : "=r"(a) : "l"(p));
    return a;
}
__device__ __forceinline__ void cp16(uint32_t dst, const void* src) {
    asm volatile("cp.async.cg.shared.global [%0], [%1], 16;" :: "r"(dst), "l"(src));
}
#define CP_COMMIT() asm volatile("cp.async.commit_group;" ::: "memory")
#define CP_WAIT(n)  asm volatile("cp.async.wait_group %0;" :: "n"(n) : "memory")

__device__ __forceinline__ uint32_t lds32(uint32_t a) {
    uint32_t v;
    asm("ld.shared.b32 %0, [%1];" : "=r"(v) : "r"(a));
    return v;
}
__device__ __forceinline__ void mma16816(float* c, const uint32_t* a, const uint32_t* b) {
    asm volatile("mma.sync.aligned.m16n8k16.row.col.f32.bf16.bf16.f32 "
        "{%0,%1,%2,%3}, {%4,%5,%6,%7}, {%8,%9}, {%0,%1,%2,%3};"
        : "+f"(c[0]), "+f"(c[1]), "+f"(c[2]), "+f"(c[3])
        : "r"(a[0]), "r"(a[1]), "r"(a[2]), "r"(a[3]), "r"(b[0]), "r"(b[1]));
}

// ---------------- K1: conv+relu stats -> BN scale/shift ----------------
__global__ __launch_bounds__(256) void k_stats(
    const float* __restrict__ x, const float* __restrict__ w,
    const float* __restrict__ bias, const float* __restrict__ gamma,
    const float* __restrict__ beta)
{
    int c = blockIdx.x;
    float wr[KERN];
#pragma unroll
    for (int i = 0; i < KERN; i++) wr[i] = w[c * KERN + i];
    float bc = bias[c];
    double s1 = 0.0, s2 = 0.0;
    for (int b = 0; b < BB; b++) {
        const float* xb = x + (size_t)b * TT;
        for (int l = threadIdx.x; l < LOUT; l += 256) {
            float h = bc;
#pragma unroll
            for (int i = 0; i < KERN; i++) h = fmaf(xb[l * STRD + i], wr[i], h);
            h = fmaxf(h, 0.0f);
            s1 += (double)h;
            s2 += (double)h * (double)h;
        }
    }
    __shared__ double r1[256], r2[256];
    r1[threadIdx.x] = s1; r2[threadIdx.x] = s2;
    __syncthreads();
    for (int off = 128; off; off >>= 1) {
        if (threadIdx.x < off) {
            r1[threadIdx.x] += r1[threadIdx.x + off];
            r2[threadIdx.x] += r2[threadIdx.x + off];
        }
        __syncthreads();
    }
    if (threadIdx.x == 0) {
        double N = (double)BB * LOUT;
        double mu = r1[0] / N;
        double var = r2[0] / N - mu * mu;
        double rs = 1.0 / sqrt(var + (double)EPSV);
        float sc = (float)((double)gamma[c] * rs);
        g_scale[c] = sc;
        g_shift[c] = beta[c] - (float)mu * sc;
    }
}

// ---------------- K2: conv+relu+BN -> d_out [B,C,L] (= z transposed) ----------------
__global__ __launch_bounds__(256) void k_norm(
    const float* __restrict__ x, const float* __restrict__ w,
    const float* __restrict__ bias, float* __restrict__ out)
{
    int l = blockIdx.x * 256 + threadIdx.x;
    int c = blockIdx.y;
    int b = blockIdx.z;
    if (l >= LOUT) return;
    float wr[KERN];
#pragma unroll
    for (int i = 0; i < KERN; i++) wr[i] = __ldg(&w[c * KERN + i]);
    float h = __ldg(&bias[c]);
    const float* xb = x + (size_t)b * TT + (size_t)l * STRD;
#pragma unroll
    for (int i = 0; i < KERN; i++) h = fmaf(xb[i], wr[i], h);
    h = fmaxf(h, 0.0f);
    out[((size_t)b * CC + c) * LOUT + l] = fmaf(h, g_scale[c], g_shift[c]);
}

// ---------------- K2b: transpose+split z -> Zf32/Zhi/Zlo [r][c] ----------------
__global__ __launch_bounds__(256) void k_prep(const float* __restrict__ zin)
{
    __shared__ float t[256][33];
    int b = blockIdx.y, l0 = blockIdx.x * 32;
    for (int i = threadIdx.x; i < 256 * 32; i += 256) {
        int c = i >> 5, l = i & 31;
        int lg = l0 + l;
        t[c][l] = (lg < LOUT) ? zin[((size_t)b * CC + c) * LOUT + lg] : 0.0f;
    }
    __syncthreads();
    for (int i = threadIdx.x; i < 32 * 256; i += 256) {
        int l = i >> 8, c = i & 255;
        int lg = l0 + l;
        if (lg >= LOUT) continue;
        size_t r = (size_t)b * LOUT + lg;
        float v = t[c][l];
        __nv_bfloat16 hi = __float2bfloat16(v);
        __nv_bfloat16 lo = __float2bfloat16(v - __bfloat162float(hi));
        g_Zf [r * CC + c] = v;
        g_Zhi[r * CC + c] = hi;
        g_Zlo[r * CC + c] = lo;
    }
}
__global__ void k_pad()
{
    int i = blockIdx.x * 256 + threadIdx.x;
    if (i < (RP - RV) * CC) {
        size_t o = (size_t)RV * CC + i;
        g_Zf[o] = 0.0f;
        g_Zhi[o] = __float2bfloat16(0.0f);
        g_Zlo[o] = __float2bfloat16(0.0f);
    }
}

// ---------------- K2c: transpose+split W -> Whi/Wlo [k][n][c] ----------------
__global__ __launch_bounds__(256) void k_wprep(const float* __restrict__ trw)
{
    __shared__ float t[32][33];
    int k = blockIdx.z, c0 = blockIdx.x * 32, n0 = blockIdx.y * 32;
    const float* W = trw + (size_t)k * CC * CC;
    for (int i = threadIdx.x; i < 32 * 32; i += 256) {
        int cc = i >> 5, nn = i & 31;
        t[cc][nn] = W[(size_t)(c0 + cc) * CC + n0 + nn];
    }
    __syncthreads();
    for (int i = threadIdx.x; i < 32 * 32; i += 256) {
        int nn = i >> 5, cc = i & 31;
        float v = t[cc][nn];
        __nv_bfloat16 hi = __float2bfloat16(v);
        __nv_bfloat16 lo = __float2bfloat16(v - __bfloat162float(hi));
        size_t o = ((size_t)k * CC + n0 + nn) * CC + c0 + cc;
        g_Whi[o] = hi;
        g_Wlo[o] = lo;
    }
}

// ---------------- K3: HMMA (mma.sync bf16, 3-pass split) + row-dot epilogue ----------------
// CTA = (k, m-tile 128). 8 warps: warp w -> mw = w>>2 (0..1), nw = w&3 (0..3);
// warp tile 64(M)x64(N) = 4x8 m16n8k16 tiles, accum 128 f32/thread.
// K chunked x64, double-buffered cp.async.
__global__ __launch_bounds__(256) void k_gemm(const float* __restrict__ trb)
{
    extern __shared__ char smem[];
    const uint32_t sb = smem_u32(smem);
    const int tid  = threadIdx.x;
    const int lane = tid & 31;
    const int w    = tid >> 5;
    const int mw   = w >> 2, nw = w & 3;
    const int k    = blockIdx.x;          // k fastest: consecutive CTAs share A tile
    const int mt   = blockIdx.y;
    const int r0   = mt * 128;
    const int rbase = mw * 64, nbase = nw * 64;

    const __nv_bfloat16* Ah = g_Zhi + (size_t)r0 * CC;
    const __nv_bfloat16* Al = g_Zlo + (size_t)r0 * CC;
    const __nv_bfloat16* Bh = g_Whi + (size_t)k * CC * CC;
    const __nv_bfloat16* Bl = g_Wlo + (size_t)k * CC * CC;

    // ---- async chunk loader: chunk co (K offset, bf16 elems) -> stage st
    auto load_chunk = [&](int co, int st) {
        uint32_t s0 = sb + st * STAGE;
#pragma unroll
        for (int t = 0; t < 4; t++) {
            int i = tid + t * 256;        // 1024 16B-ops per A matrix
            int row = i >> 3, u = i & 7;
            uint32_t d = (uint32_t)(row * 144 + u * 16);
            const __nv_bfloat16* sA = Ah + (size_t)row * CC + co + u * 8;
            const __nv_bfloat16* sL = Al + (size_t)row * CC + co + u * 8;
            cp16(s0 + OFF_AHI + d, sA);
            cp16(s0 + OFF_ALO + d, sL);
        }
#pragma unroll
        for (int t = 0; t < 8; t++) {
            int i = tid + t * 256;        // 2048 16B-ops per B matrix
            int row = i >> 3, u = i & 7;
            uint32_t d = (uint32_t)(row * 144 + u * 16);
            cp16(s0 + OFF_BHI + d, Bh + (size_t)row * CC + co + u * 8);
            cp16(s0 + OFF_BLO + d, Bl + (size_t)row * CC + co + u * 8);
        }
        CP_COMMIT();
    };

    float c[4][8][4];
#pragma unroll
    for (int mi = 0; mi < 4; mi++)
#pragma unroll
        for (int ni = 0; ni < 8; ni++)
#pragma unroll
            for (int j = 0; j < 4; j++) c[mi][ni][j] = 0.0f;

    load_chunk(0, 0);

    for (int kc = 0; kc < 4; kc++) {
        if (kc < 3) load_chunk((kc + 1) * 64, (kc + 1) & 1);
        if (kc < 3) { CP_WAIT(1); } else { CP_WAIT(0); }
        __syncthreads();

        const uint32_t st = sb + (kc & 1) * STAGE;
        const uint32_t aBaseH = st + OFF_AHI + (uint32_t)((rbase + (lane >> 2)) * 144 + (lane & 3) * 4);
        const uint32_t aBaseL = st + OFF_ALO + (uint32_t)((rbase + (lane >> 2)) * 144 + (lane & 3) * 4);
        const uint32_t bBaseH = st + OFF_BHI + (uint32_t)((nbase + (lane >> 2)) * 144 + (lane & 3) * 4);
        const uint32_t bBaseL = st + OFF_BLO + (uint32_t)((nbase + (lane >> 2)) * 144 + (lane & 3) * 4);

#pragma unroll
        for (int ks = 0; ks < 4; ks++) {
            const uint32_t kof = ks * 32;
            uint32_t aH[4][4], bH[8][2];
#pragma unroll
            for (int mi = 0; mi < 4; mi++) {
                uint32_t ad = aBaseH + mi * (16 * 144) + kof;
                aH[mi][0] = lds32(ad);
                aH[mi][1] = lds32(ad + 8 * 144);
                aH[mi][2] = lds32(ad + 16);
                aH[mi][3] = lds32(ad + 8 * 144 + 16);
            }
#pragma unroll
            for (int ni = 0; ni < 8; ni++) {
                uint32_t bd = bBaseH + ni * (8 * 144) + kof;
                bH[ni][0] = lds32(bd);
                bH[ni][1] = lds32(bd + 16);
            }
            // pass 0: hi * hi
#pragma unroll
            for (int mi = 0; mi < 4; mi++)
#pragma unroll
                for (int ni = 0; ni < 8; ni++) mma16816(c[mi][ni], aH[mi], bH[ni]);
            // pass 1: lo * hi
            {
                uint32_t aL[4][4];
#pragma unroll
                for (int mi = 0; mi < 4; mi++) {
                    uint32_t ad = aBaseL + mi * (16 * 144) + kof;
                    aL[mi][0] = lds32(ad);
                    aL[mi][1] = lds32(ad + 8 * 144);
                    aL[mi][2] = lds32(ad + 16);
                    aL[mi][3] = lds32(ad + 8 * 144 + 16);
                }
#pragma unroll
                for (int mi = 0; mi < 4; mi++)
#pragma unroll
                    for (int ni = 0; ni < 8; ni++) mma16816(c[mi][ni], aL[mi], bH[ni]);
            }
            // pass 2: hi * lo
            {
                uint32_t bL[8][2];
#pragma unroll
                for (int ni = 0; ni < 8; ni++) {
                    uint32_t bd = bBaseL + ni * (8 * 144) + kof;
                    bL[ni][0] = lds32(bd);
                    bL[ni][1] = lds32(bd + 16);
                }
#pragma unroll
                for (int mi = 0; mi < 4; mi++)
#pragma unroll
                    for (int ni = 0; ni < 8; ni++) mma16816(c[mi][ni], aH[mi], bL[ni]);
            }
        }
        __syncthreads();
    }

    // ---- epilogue: Q[r] = sum_n (U[r,n] + b_n) * zf[r,n]
    float2 bias[8];
#pragma unroll
    for (int ni = 0; ni < 8; ni++)
        bias[ni] = __ldg((const float2*)&trb[k * CC + nbase + ni * 8 + (lane & 3) * 2]);

    float* red = (float*)(smem + OFF_RED);
    float qlo[4], qhi[4];
#pragma unroll
    for (int mi = 0; mi < 4; mi++) { qlo[mi] = 0.0f; qhi[mi] = 0.0f; }
#pragma unroll
    for (int mi = 0; mi < 4; mi++) {
        int rlo = r0 + rbase + mi * 16 + (lane >> 2);
#pragma unroll
        for (int ni = 0; ni < 8; ni++) {
            int col = nbase + ni * 8 + (lane & 3) * 2;
            float2 zl = *(const float2*)&g_Zf[(size_t)rlo * CC + col];
            float2 zh = *(const float2*)&g_Zf[(size_t)(rlo + 8) * CC + col];
            qlo[mi] = fmaf(c[mi][ni][0] + bias[ni].x, zl.x, qlo[mi]);
            qlo[mi] = fmaf(c[mi][ni][1] + bias[ni].y, zl.y, qlo[mi]);
            qhi[mi] = fmaf(c[mi][ni][2] + bias[ni].x, zh.x, qhi[mi]);
            qhi[mi] = fmaf(c[mi][ni][3] + bias[ni].y, zh.y, qhi[mi]);
        }
    }
#pragma unroll
    for (int m = 1; m <= 2; m <<= 1) {
#pragma unroll
        for (int mi = 0; mi < 4; mi++) {
            qlo[mi] += __shfl_xor_sync(0xffffffffu, qlo[mi], m);
            qhi[mi] += __shfl_xor_sync(0xffffffffu, qhi[mi], m);
        }
    }
    if ((lane & 3) == 0) {
#pragma unroll
        for (int mi = 0; mi < 4; mi++) {
            int rowt = rbase + mi * 16 + (lane >> 2);
            red[nw * 128 + rowt]     = qlo[mi];
            red[nw * 128 + rowt + 8] = qhi[mi];
        }
    }
    __syncthreads();
    if (tid < 128) {
        float q = red[tid] + red[128 + tid] + red[256 + tid] + red[384 + tid];
        int r = r0 + tid;
        if (r < RV) {
            int b = r / LOUT, l = r - b * LOUT;
            g_Q[((size_t)k * BB + b) * LOUT + l] = q;
        }
    }
}

// ---------------- K4: losses (reference's flat-reshape softmax rows) ----------------
__global__ __launch_bounds__(256) void k_loss_part(const int* __restrict__ perm)
{
    const int k = blockIdx.x + 1;
    const int b = blockIdx.y;
    const int llen = LOUT - k;
    const float* Qk = g_Q + (size_t)(k - 1) * BB * LOUT;
    double acc = 0.0;
    for (int r = threadIdx.x; r < llen; r += 256) {
        int idx = 11 * r;
        int s = idx / llen;
        int i = idx - s * llen;
        float f[NNEG + 1];
#pragma unroll
        for (int j = 0; j <= NNEG; j++) {
            float v;
            if (s == 0) v = Qk[b * LOUT + k + i];
            else {
                int bb2 = (b - s) & (BB - 1);
                v = Qk[bb2 * LOUT + __ldg(&perm[k + i])];
            }
            f[j] = v;
            i++;
            if (i == llen) { i = 0; s++; }
        }
        float mx = f[0];
#pragma unroll
        for (int j = 1; j <= NNEG; j++) mx = fmaxf(mx, f[j]);
        float se = 0.0f, sf = 0.0f;
#pragma unroll
        for (int j = 0; j <= NNEG; j++) { se += __expf(f[j] - mx); sf += f[j]; }
        float lse = mx + __logf(se);
        acc += (double)((NNEG + 1) * lse - sf);
    }
    __shared__ double rsh[256];
    rsh[threadIdx.x] = acc;
    __syncthreads();
    for (int off = 128; off; off >>= 1) {
        if (threadIdx.x < off) rsh[threadIdx.x] += rsh[threadIdx.x + off];
        __syncthreads();
    }
    if (threadIdx.x == 0) g_part[(k - 1) * BB + b] = rsh[0];
}
__global__ __launch_bounds__(32) void k_loss_fin(float* __restrict__ out_losses)
{
    int kk = threadIdx.x;
    if (kk >= KST) return;
    int k = kk + 1;
    int llen = LOUT - k;
    double s = 0.0;
#pragma unroll
    for (int b = 0; b < BB; b++) s += g_part[kk * BB + b];
    out_losses[kk] = (float)(s / ((double)(llen - k) * BB));
}

// ---------------- launch ----------------
extern "C" void kernel_launch(void* const* d_in, const int* in_sizes, int n_in,
                              void* d_out, int out_size)
{
    const float* x      = (const float*)d_in[0];
    const float* conv_w = (const float*)d_in[1];
    const float* conv_b = (const float*)d_in[2];
    const float* gamma  = (const float*)d_in[3];
    const float* beta   = (const float*)d_in[4];
    const float* trw    = (const float*)d_in[5];
    const float* trb    = (const float*)d_in[6];
    const int*   perm   = (const int*)d_in[7];
    float* out = (float*)d_out;

    cudaFuncSetAttribute(k_gemm, cudaFuncAttributeMaxDynamicSharedMemorySize, SMEM_DYN);

    k_stats<<<CC, 256>>>(x, conv_w, conv_b, gamma, beta);

    dim3 g2((LOUT + 255) / 256, CC, BB);
    k_norm<<<g2, 256>>>(x, conv_w, conv_b, out);

    dim3 gp(64, BB);
    k_prep<<<gp, 256>>>(out);
    k_pad<<<((RP - RV) * CC + 255) / 256, 256>>>();

    dim3 gw(8, 8, KST);
    k_wprep<<<gw, 256>>>(trw);

    dim3 gg(KST, NTILE);          // k fastest -> adjacent CTAs reuse A from L2
    k_gemm<<<gg, 256, SMEM_DYN>>>(trb);

    dim3 g4(KST, BB);
    k_loss_part<<<g4, 256>>>(perm);
    k_loss_fin<<<1, 32>>>(out + (size_t)BB * CC * LOUT);
}

// round 6
// speedup vs baseline: 2.9659x; 1.0875x over previous
#include <cuda_runtime.h>
#include <cuda_bf16.h>
#include <math.h>
#include <stdint.h>

#define BB    16
#define TT    10240
#define CC    256
#define KERN  10
#define STRD  5
#define LOUT  2047
#define KST   12
#define NNEG  10
#define EPSV  1e-5f
#define RV    32752          // B*LOUT valid rows
#define RP    32768          // padded rows (256 tiles x 128)
#define NTILE 256            // M-tiles of 128

// ---- GEMM smem layout (bytes). Row stride 144B (36 banks) => conflict-free LDS.
#define OFF_AHI 0
#define OFF_ALO 18432
#define OFF_BHI 36864
#define OFF_BLO 73728
#define STAGE   110592
#define OFF_RED (2 * STAGE)               // 221184: float red[4][128]
#define SMEM_DYN (OFF_RED + 2048)         // 223232

// ---------------- device scratch (no allocation allowed) ----------------
__device__ __align__(16) float         g_scale[CC];
__device__ __align__(16) float         g_shift[CC];
__device__ __align__(16) double        g_sp1[CC * 8];
__device__ __align__(16) double        g_sp2[CC * 8];
__device__ __align__(16) float         g_Q[(size_t)KST * BB * LOUT];
__device__ __align__(16) double        g_part[KST * BB];
__device__ __align__(16) float         g_Zf [(size_t)RP * CC];
__device__ __align__(16) __nv_bfloat16 g_Zhi[(size_t)RP * CC];
__device__ __align__(16) __nv_bfloat16 g_Zlo[(size_t)RP * CC];
__device__ __align__(16) __nv_bfloat16 g_Whi[(size_t)KST * CC * CC];  // [k][n][c] = W[c][n]
__device__ __align__(16) __nv_bfloat16 g_Wlo[(size_t)KST * CC * CC];

// ---------------- helpers (baseline sm_80+ PTX only) ----------------
__device__ __forceinline__ uint32_t smem_u32(const void* p) {
    uint32_t a;
    asm("{ .reg .u64 t; cvta.to.shared.u64 t, %1; cvt.u32.u64 %0, t; }" : "=r"(a) : "l"(p));
    return a;
}
__device__ __forceinline__ void cp16(uint32_t dst, const void* src) {
    asm volatile("cp.async.cg.shared.global [%0], [%1], 16;" :: "r"(dst), "l"(src));
}
#define CP_COMMIT() asm volatile("cp.async.commit_group;" ::: "memory")
#define CP_WAIT(n)  asm volatile("cp.async.wait_group %0;" :: "n"(n) : "memory")

__device__ __forceinline__ uint32_t lds32(uint32_t a) {
    uint32_t v;
    asm("ld.shared.b32 %0, [%1];" : "=r"(v) : "r"(a));
    return v;
}
__device__ __forceinline__ void mma16816(float* c, const uint32_t* a, const uint32_t* b) {
    asm volatile("mma.sync.aligned.m16n8k16.row.col.f32.bf16.bf16.f32 "
        "{%0,%1,%2,%3}, {%4,%5,%6,%7}, {%8,%9}, {%0,%1,%2,%3};"
        : "+f"(c[0]), "+f"(c[1]), "+f"(c[2]), "+f"(c[3])
        : "r"(a[0]), "r"(a[1]), "r"(a[2]), "r"(a[3]), "r"(b[0]), "r"(b[1]));
}

// ---------------- K1a: conv+relu partial stats (c x 8 b-chunks) ----------------
__global__ __launch_bounds__(256) void k_stats_p(
    const float* __restrict__ x, const float* __restrict__ w,
    const float* __restrict__ bias)
{
    int c = blockIdx.x, ch = blockIdx.y;      // chunk = 2 batches
    float wr[KERN];
#pragma unroll
    for (int i = 0; i < KERN; i++) wr[i] = w[c * KERN + i];
    float bc = bias[c];
    double s1 = 0.0, s2 = 0.0;
    for (int bb = 0; bb < 2; bb++) {
        const float* xb = x + (size_t)(ch * 2 + bb) * TT;
        for (int l = threadIdx.x; l < LOUT; l += 256) {
            float h = bc;
#pragma unroll
            for (int i = 0; i < KERN; i++) h = fmaf(xb[l * STRD + i], wr[i], h);
            h = fmaxf(h, 0.0f);
            s1 += (double)h;
            s2 += (double)h * (double)h;
        }
    }
    __shared__ double r1[256], r2[256];
    r1[threadIdx.x] = s1; r2[threadIdx.x] = s2;
    __syncthreads();
    for (int off = 128; off; off >>= 1) {
        if (threadIdx.x < off) {
            r1[threadIdx.x] += r1[threadIdx.x + off];
            r2[threadIdx.x] += r2[threadIdx.x + off];
        }
        __syncthreads();
    }
    if (threadIdx.x == 0) { g_sp1[c * 8 + ch] = r1[0]; g_sp2[c * 8 + ch] = r2[0]; }
}

// ---------------- K1b: finalize BN scale/shift ----------------
__global__ __launch_bounds__(256) void k_stats_f(
    const float* __restrict__ gamma, const float* __restrict__ beta)
{
    int c = threadIdx.x;
    double s1 = 0.0, s2 = 0.0;
#pragma unroll
    for (int j = 0; j < 8; j++) { s1 += g_sp1[c * 8 + j]; s2 += g_sp2[c * 8 + j]; }
    double N = (double)BB * LOUT;
    double mu = s1 / N;
    double var = s2 / N - mu * mu;
    double rs = 1.0 / sqrt(var + (double)EPSV);
    float sc = (float)((double)gamma[c] * rs);
    g_scale[c] = sc;
    g_shift[c] = beta[c] - (float)mu * sc;
}

// ---------------- K2: fused conv+relu+BN -> d_out [B,C,L] AND Zf/Zhi/Zlo [r][c] ----
__global__ __launch_bounds__(256) void k_fuse(
    const float* __restrict__ x, const float* __restrict__ w,
    const float* __restrict__ bias, float* __restrict__ out)
{
    __shared__ float xs[168];
    __shared__ float ht[CC][33];
    const int tid = threadIdx.x;
    const int l0 = blockIdx.x * 32;
    const int b  = blockIdx.y;

    // x segment for l in [l0, l0+32): indices [l0*5, l0*5+165)
    const int base = l0 * STRD;
    for (int i = tid; i < 165; i += 256) {
        int g = base + i;
        xs[i] = (g < TT) ? x[(size_t)b * TT + g] : 0.0f;
    }
    __syncthreads();

    // thread = channel: compute 32 h values from smem broadcast
    {
        const int c = tid;
        float wr[KERN];
#pragma unroll
        for (int i = 0; i < KERN; i++) wr[i] = __ldg(&w[c * KERN + i]);
        const float bc = __ldg(&bias[c]);
        const float sc = g_scale[c], sh = g_shift[c];
#pragma unroll
        for (int l = 0; l < 32; l++) {
            float h = bc;
#pragma unroll
            for (int i = 0; i < KERN; i++) h = fmaf(xs[l * STRD + i], wr[i], h);
            h = fmaxf(h, 0.0f);
            ht[c][l] = fmaf(h, sc, sh);
        }
    }
    __syncthreads();

    // write d_out[b,c,l] coalesced along l (warp lane = l)
    {
        const int l = tid & 31;
        const int lg = l0 + l;
        if (lg < LOUT) {
#pragma unroll
            for (int j = 0; j < 32; j++) {
                int c = (tid >> 5) + j * 8;
                out[((size_t)b * CC + c) * LOUT + lg] = ht[c][l];
            }
        }
    }

    // write Z arrays [r][c]: c = tid -> coalesced; ht[tid][l] bank=(tid+l)%32 conflict-free
    {
        const int c = tid;
#pragma unroll 4
        for (int l = 0; l < 32; l++) {
            int lg = l0 + l;
            if (lg >= LOUT) break;
            size_t r = (size_t)b * LOUT + lg;
            float v = ht[c][l];
            __nv_bfloat16 hi = __float2bfloat16(v);
            __nv_bfloat16 lo = __float2bfloat16(v - __bfloat162float(hi));
            g_Zf [r * CC + c] = v;
            g_Zhi[r * CC + c] = hi;
            g_Zlo[r * CC + c] = lo;
        }
    }
}

__global__ void k_pad()
{
    int i = blockIdx.x * 256 + threadIdx.x;
    if (i < (RP - RV) * CC) {
        size_t o = (size_t)RV * CC + i;
        g_Zf[o] = 0.0f;
        g_Zhi[o] = __float2bfloat16(0.0f);
        g_Zlo[o] = __float2bfloat16(0.0f);
    }
}

// ---------------- K2c: transpose+split W -> Whi/Wlo [k][n][c] ----------------
__global__ __launch_bounds__(256) void k_wprep(const float* __restrict__ trw)
{
    __shared__ float t[32][33];
    int k = blockIdx.z, c0 = blockIdx.x * 32, n0 = blockIdx.y * 32;
    const float* W = trw + (size_t)k * CC * CC;
    for (int i = threadIdx.x; i < 32 * 32; i += 256) {
        int cc = i >> 5, nn = i & 31;
        t[cc][nn] = W[(size_t)(c0 + cc) * CC + n0 + nn];
    }
    __syncthreads();
    for (int i = threadIdx.x; i < 32 * 32; i += 256) {
        int nn = i >> 5, cc = i & 31;
        float v = t[cc][nn];
        __nv_bfloat16 hi = __float2bfloat16(v);
        __nv_bfloat16 lo = __float2bfloat16(v - __bfloat162float(hi));
        size_t o = ((size_t)k * CC + n0 + nn) * CC + c0 + cc;
        g_Whi[o] = hi;
        g_Wlo[o] = lo;
    }
}

// ---------------- K3: HMMA (mma.sync bf16, 3-pass split) + row-dot epilogue ----------------
__global__ __launch_bounds__(256) void k_gemm(const float* __restrict__ trb)
{
    extern __shared__ char smem[];
    const uint32_t sb = smem_u32(smem);
    const int tid  = threadIdx.x;
    const int lane = tid & 31;
    const int w    = tid >> 5;
    const int mw   = w >> 2, nw = w & 3;
    const int k    = blockIdx.x;          // k fastest: consecutive CTAs share A tile
    const int mt   = blockIdx.y;
    const int r0   = mt * 128;
    const int rbase = mw * 64, nbase = nw * 64;

    const __nv_bfloat16* Ah = g_Zhi + (size_t)r0 * CC;
    const __nv_bfloat16* Al = g_Zlo + (size_t)r0 * CC;
    const __nv_bfloat16* Bh = g_Whi + (size_t)k * CC * CC;
    const __nv_bfloat16* Bl = g_Wlo + (size_t)k * CC * CC;

    auto load_chunk = [&](int co, int st) {
        uint32_t s0 = sb + st * STAGE;
#pragma unroll
        for (int t = 0; t < 4; t++) {
            int i = tid + t * 256;
            int row = i >> 3, u = i & 7;
            uint32_t d = (uint32_t)(row * 144 + u * 16);
            cp16(s0 + OFF_AHI + d, Ah + (size_t)row * CC + co + u * 8);
            cp16(s0 + OFF_ALO + d, Al + (size_t)row * CC + co + u * 8);
        }
#pragma unroll
        for (int t = 0; t < 8; t++) {
            int i = tid + t * 256;
            int row = i >> 3, u = i & 7;
            uint32_t d = (uint32_t)(row * 144 + u * 16);
            cp16(s0 + OFF_BHI + d, Bh + (size_t)row * CC + co + u * 8);
            cp16(s0 + OFF_BLO + d, Bl + (size_t)row * CC + co + u * 8);
        }
        CP_COMMIT();
    };

    float c[4][8][4];
#pragma unroll
    for (int mi = 0; mi < 4; mi++)
#pragma unroll
        for (int ni = 0; ni < 8; ni++)
#pragma unroll
            for (int j = 0; j < 4; j++) c[mi][ni][j] = 0.0f;

    load_chunk(0, 0);

    for (int kc = 0; kc < 4; kc++) {
        if (kc < 3) load_chunk((kc + 1) * 64, (kc + 1) & 1);
        if (kc < 3) { CP_WAIT(1); } else { CP_WAIT(0); }
        __syncthreads();

        const uint32_t st = sb + (kc & 1) * STAGE;
        const uint32_t aBaseH = st + OFF_AHI + (uint32_t)((rbase + (lane >> 2)) * 144 + (lane & 3) * 4);
        const uint32_t aBaseL = st + OFF_ALO + (uint32_t)((rbase + (lane >> 2)) * 144 + (lane & 3) * 4);
        const uint32_t bBaseH = st + OFF_BHI + (uint32_t)((nbase + (lane >> 2)) * 144 + (lane & 3) * 4);
        const uint32_t bBaseL = st + OFF_BLO + (uint32_t)((nbase + (lane >> 2)) * 144 + (lane & 3) * 4);

#pragma unroll
        for (int ks = 0; ks < 4; ks++) {
            const uint32_t kof = ks * 32;
            uint32_t aH[4][4], bH[8][2];
#pragma unroll
            for (int mi = 0; mi < 4; mi++) {
                uint32_t ad = aBaseH + mi * (16 * 144) + kof;
                aH[mi][0] = lds32(ad);
                aH[mi][1] = lds32(ad + 8 * 144);
                aH[mi][2] = lds32(ad + 16);
                aH[mi][3] = lds32(ad + 8 * 144 + 16);
            }
#pragma unroll
            for (int ni = 0; ni < 8; ni++) {
                uint32_t bd = bBaseH + ni * (8 * 144) + kof;
                bH[ni][0] = lds32(bd);
                bH[ni][1] = lds32(bd + 16);
            }
#pragma unroll
            for (int mi = 0; mi < 4; mi++)
#pragma unroll
                for (int ni = 0; ni < 8; ni++) mma16816(c[mi][ni], aH[mi], bH[ni]);
            {
                uint32_t aL[4][4];
#pragma unroll
                for (int mi = 0; mi < 4; mi++) {
                    uint32_t ad = aBaseL + mi * (16 * 144) + kof;
                    aL[mi][0] = lds32(ad);
                    aL[mi][1] = lds32(ad + 8 * 144);
                    aL[mi][2] = lds32(ad + 16);
                    aL[mi][3] = lds32(ad + 8 * 144 + 16);
                }
#pragma unroll
                for (int mi = 0; mi < 4; mi++)
#pragma unroll
                    for (int ni = 0; ni < 8; ni++) mma16816(c[mi][ni], aL[mi], bH[ni]);
            }
            {
                uint32_t bL[8][2];
#pragma unroll
                for (int ni = 0; ni < 8; ni++) {
                    uint32_t bd = bBaseL + ni * (8 * 144) + kof;
                    bL[ni][0] = lds32(bd);
                    bL[ni][1] = lds32(bd + 16);
                }
#pragma unroll
                for (int mi = 0; mi < 4; mi++)
#pragma unroll
                    for (int ni = 0; ni < 8; ni++) mma16816(c[mi][ni], aH[mi], bL[ni]);
            }
        }
        __syncthreads();
    }

    // ---- epilogue: Q[r] = sum_n (U[r,n] + b_n) * zf[r,n]
    float2 bias[8];
#pragma unroll
    for (int ni = 0; ni < 8; ni++)
        bias[ni] = __ldg((const float2*)&trb[k * CC + nbase + ni * 8 + (lane & 3) * 2]);

    float* red = (float*)(smem + OFF_RED);
    float qlo[4], qhi[4];
#pragma unroll
    for (int mi = 0; mi < 4; mi++) { qlo[mi] = 0.0f; qhi[mi] = 0.0f; }
#pragma unroll
    for (int mi = 0; mi < 4; mi++) {
        int rlo = r0 + rbase + mi * 16 + (lane >> 2);
#pragma unroll
        for (int ni = 0; ni < 8; ni++) {
            int col = nbase + ni * 8 + (lane & 3) * 2;
            float2 zl = *(const float2*)&g_Zf[(size_t)rlo * CC + col];
            float2 zh = *(const float2*)&g_Zf[(size_t)(rlo + 8) * CC + col];
            qlo[mi] = fmaf(c[mi][ni][0] + bias[ni].x, zl.x, qlo[mi]);
            qlo[mi] = fmaf(c[mi][ni][1] + bias[ni].y, zl.y, qlo[mi]);
            qhi[mi] = fmaf(c[mi][ni][2] + bias[ni].x, zh.x, qhi[mi]);
            qhi[mi] = fmaf(c[mi][ni][3] + bias[ni].y, zh.y, qhi[mi]);
        }
    }
#pragma unroll
    for (int m = 1; m <= 2; m <<= 1) {
#pragma unroll
        for (int mi = 0; mi < 4; mi++) {
            qlo[mi] += __shfl_xor_sync(0xffffffffu, qlo[mi], m);
            qhi[mi] += __shfl_xor_sync(0xffffffffu, qhi[mi], m);
        }
    }
    if ((lane & 3) == 0) {
#pragma unroll
        for (int mi = 0; mi < 4; mi++) {
            int rowt = rbase + mi * 16 + (lane >> 2);
            red[nw * 128 + rowt]     = qlo[mi];
            red[nw * 128 + rowt + 8] = qhi[mi];
        }
    }
    __syncthreads();
    if (tid < 128) {
        float q = red[tid] + red[128 + tid] + red[256 + tid] + red[384 + tid];
        int r = r0 + tid;
        if (r < RV) {
            int b = r / LOUT, l = r - b * LOUT;
            g_Q[((size_t)k * BB + b) * LOUT + l] = q;
        }
    }
}

// ---------------- K4: losses (reference's flat-reshape softmax rows) ----------------
__global__ __launch_bounds__(256) void k_loss_part(const int* __restrict__ perm)
{
    const int k = blockIdx.x + 1;
    const int b = blockIdx.y;
    const int llen = LOUT - k;
    const float* Qk = g_Q + (size_t)(k - 1) * BB * LOUT;
    double acc = 0.0;
    for (int r = threadIdx.x; r < llen; r += 256) {
        int idx = 11 * r;
        int s = idx / llen;
        int i = idx - s * llen;
        float f[NNEG + 1];
#pragma unroll
        for (int j = 0; j <= NNEG; j++) {
            float v;
            if (s == 0) v = Qk[b * LOUT + k + i];
            else {
                int bb2 = (b - s) & (BB - 1);
                v = Qk[bb2 * LOUT + __ldg(&perm[k + i])];
            }
            f[j] = v;
            i++;
            if (i == llen) { i = 0; s++; }
        }
        float mx = f[0];
#pragma unroll
        for (int j = 1; j <= NNEG; j++) mx = fmaxf(mx, f[j]);
        float se = 0.0f, sf = 0.0f;
#pragma unroll
        for (int j = 0; j <= NNEG; j++) { se += __expf(f[j] - mx); sf += f[j]; }
        float lse = mx + __logf(se);
        acc += (double)((NNEG + 1) * lse - sf);
    }
    __shared__ double rsh[256];
    rsh[threadIdx.x] = acc;
    __syncthreads();
    for (int off = 128; off; off >>= 1) {
        if (threadIdx.x < off) rsh[threadIdx.x] += rsh[threadIdx.x + off];
        __syncthreads();
    }
    if (threadIdx.x == 0) g_part[(k - 1) * BB + b] = rsh[0];
}
__global__ __launch_bounds__(32) void k_loss_fin(float* __restrict__ out_losses)
{
    int kk = threadIdx.x;
    if (kk >= KST) return;
    int k = kk + 1;
    int llen = LOUT - k;
    double s = 0.0;
#pragma unroll
    for (int b = 0; b < BB; b++) s += g_part[kk * BB + b];
    out_losses[kk] = (float)(s / ((double)(llen - k) * BB));
}

// ---------------- launch ----------------
extern "C" void kernel_launch(void* const* d_in, const int* in_sizes, int n_in,
                              void* d_out, int out_size)
{
    const float* x      = (const float*)d_in[0];
    const float* conv_w = (const float*)d_in[1];
    const float* conv_b = (const float*)d_in[2];
    const float* gamma  = (const float*)d_in[3];
    const float* beta   = (const float*)d_in[4];
    const float* trw    = (const float*)d_in[5];
    const float* trb    = (const float*)d_in[6];
    const int*   perm   = (const int*)d_in[7];
    float* out = (float*)d_out;

    cudaFuncSetAttribute(k_gemm, cudaFuncAttributeMaxDynamicSharedMemorySize, SMEM_DYN);

    dim3 gs(CC, 8);
    k_stats_p<<<gs, 256>>>(x, conv_w, conv_b);
    k_stats_f<<<1, 256>>>(gamma, beta);

    dim3 gf(64, BB);
    k_fuse<<<gf, 256>>>(x, conv_w, conv_b, out);
    k_pad<<<((RP - RV) * CC + 255) / 256, 256>>>();

    dim3 gw(8, 8, KST);
    k_wprep<<<gw, 256>>>(trw);

    dim3 gg(KST, NTILE);          // k fastest -> adjacent CTAs reuse A from L2
    k_gemm<<<gg, 256, SMEM_DYN>>>(trb);

    dim3 g4(KST, BB);
    k_loss_part<<<g4, 256>>>(perm);
    k_loss_fin<<<1, 32>>>(out + (size_t)BB * CC * LOUT);
}